// round 13
// baseline (speedup 1.0000x reference)
#include <cuda_runtime.h>
#include <cuda_fp16.h>
#include <cstdint>

// Deformable conv2d B=8, Cin=Cout=128, H=W=64, 3x3 s1 p1 DG=1.
// f16 HMMA m16n8k16 (fp32 accum). Channel-packed fp16 X window (LDS.128 = 8ch),
// precomputed per-unit gather addresses (step-invariant), ldmatrix B feed,
// lane-contig A LDG.128. One CTA per (b, ho-pair): 256 CTAs, 16 steps of K=72.

#define THREADS 256
static constexpr int KTOT = 1152;
static constexpr int NSTEP = 16;            // one cg8 per step, K=72

static constexpr int XROWS = 13;
static constexpr int XWIN4 = XROWS * 64;    // uint4 per window buffer = 832
static constexpr int XWINB = XWIN4 * 16;    // bytes per window buffer = 13312
static constexpr int BSTR  = 36;            // B row stride in u32 (72 half, 144B)
static constexpr int BBUF  = 128 * BSTR;    // 4608 u32 per buffer
static constexpr int BBUFB = BBUF * 4;      // 18432 B

// smem layout (bytes)
static constexpr int OFF_MI = 0;            // int[1152]      4608
static constexpr int OFF_MW = 4608;         // float4[1152]  18432
static constexpr int OFF_AD = 23040;        // uint2[1152]    9216
static constexpr int OFF_X  = 32256;        // 2 x 13312 =   26624
static constexpr int OFF_B  = 58880;        // 2 x 18432 =   36864
static constexpr int SMEM_TOTAL = 95744;

#define SWZ(x) ((x) ^ (((x) >> 3) & 7))

// A weights, lane-contiguous uint4: [step][tapgrp(2)][row(128)][tq(4)]
__device__ uint4    g_wtA[NSTEP * 2 * 128 * 4];
// tap-8 tail: [step][row][tq]
__device__ uint32_t g_wtA8[NSTEP * 128 * 4];

__device__ __forceinline__ void mma_k16(float* d, uint32_t a0, uint32_t a1,
                                        uint32_t a2, uint32_t a3,
                                        uint32_t b0, uint32_t b1) {
    asm volatile(
        "mma.sync.aligned.m16n8k16.row.col.f32.f16.f16.f32 "
        "{%0,%1,%2,%3}, {%4,%5,%6,%7}, {%8,%9}, {%0,%1,%2,%3};"
        : "+f"(d[0]), "+f"(d[1]), "+f"(d[2]), "+f"(d[3])
        : "r"(a0), "r"(a1), "r"(a2), "r"(a3), "r"(b0), "r"(b1));
}
__device__ __forceinline__ void mma_k8(float* d, uint32_t a0, uint32_t a1,
                                       uint32_t b0) {
    asm volatile(
        "mma.sync.aligned.m16n8k8.row.col.f32.f16.f16.f32 "
        "{%0,%1,%2,%3}, {%4,%5}, {%6}, {%0,%1,%2,%3};"
        : "+f"(d[0]), "+f"(d[1]), "+f"(d[2]), "+f"(d[3])
        : "r"(a0), "r"(a1), "r"(b0));
}
__device__ __forceinline__ void ldsm4(uint32_t* r, uint32_t addr) {
    asm volatile(
        "ldmatrix.sync.aligned.m8n8.x4.shared.b16 {%0,%1,%2,%3}, [%4];"
        : "=r"(r[0]), "=r"(r[1]), "=r"(r[2]), "=r"(r[3]) : "r"(addr));
}
__device__ __forceinline__ uint32_t h2u(__half2 h) { return *(uint32_t*)&h; }

__global__ void wt_permute(const float* __restrict__ w) {
    int idx = blockIdx.x * 256 + threadIdx.x;
    if (idx >= NSTEP * 128 * 4) return;
    int tq = idx & 3, row = (idx >> 2) & 127, s = idx >> 9;
    int ch0 = s * 8 + 2 * tq;
    const float* w0 = w + row * KTOT + ch0 * 9;
    const float* w1 = w0 + 9;
    #pragma unroll
    for (int tg = 0; tg < 2; tg++) {
        uint4 v;
        v.x = h2u(__floats2half2_rn(w0[4 * tg + 0], w1[4 * tg + 0]));
        v.y = h2u(__floats2half2_rn(w0[4 * tg + 1], w1[4 * tg + 1]));
        v.z = h2u(__floats2half2_rn(w0[4 * tg + 2], w1[4 * tg + 2]));
        v.w = h2u(__floats2half2_rn(w0[4 * tg + 3], w1[4 * tg + 3]));
        g_wtA[((s * 2 + tg) * 128 + row) * 4 + tq] = v;
    }
    g_wtA8[idx] = h2u(__floats2half2_rn(w0[8], w1[8]));
}

// stage one (row, x-quad) of a window: 8 coalesced LDG.128 + 4 swizzled STS.128
__device__ __forceinline__ void stage_unit(uint4* xw4, const float* xcb,
                                           int u, int lo) {
    int r = u >> 4, q = u & 15;
    const float* src = xcb + (lo + r) * 64 + 4 * q;
    uint32_t h[4][4];
    #pragma unroll
    for (int p = 0; p < 4; p++) {
        float4 a = *(const float4*)(src + (2 * p) * 4096);
        float4 b = *(const float4*)(src + (2 * p + 1) * 4096);
        h[0][p] = h2u(__floats2half2_rn(a.x, b.x));
        h[1][p] = h2u(__floats2half2_rn(a.y, b.y));
        h[2][p] = h2u(__floats2half2_rn(a.z, b.z));
        h[3][p] = h2u(__floats2half2_rn(a.w, b.w));
    }
    #pragma unroll
    for (int i = 0; i < 4; i++) {
        int x = 4 * q + i;
        xw4[r * 64 + SWZ(x)] = make_uint4(h[i][0], h[i][1], h[i][2], h[i][3]);
    }
}

// gather one (tap, px): precomputed addresses, 4 LDS.128 corners -> 1 STS.128
__device__ __forceinline__ void gather_unit(const char* xwb, const float* xcb,
                                            uint32_t* bD, const uint2* sAD,
                                            const int* sMI, const float4* sMW,
                                            int idx) {
    const int px = idx & 127, tap = idx >> 7;
    const int u = tap * 128 + px;
    uint2 ad = sAD[u];
    float4 mw = sMW[u];
    uint32_t ov[4];
    if (ad.x != 0xFFFFFFFFu) {
        uint32_t c00[4], c01[4], c10[4], c11[4];
        *(uint4*)c00 = *(const uint4*)(xwb + (ad.x & 0xFFFFu));
        *(uint4*)c01 = *(const uint4*)(xwb + (ad.x >> 16));
        *(uint4*)c10 = *(const uint4*)(xwb + (ad.y & 0xFFFFu));
        *(uint4*)c11 = *(const uint4*)(xwb + (ad.y >> 16));
        #pragma unroll
        for (int jj = 0; jj < 4; jj++) {
            float2 f00 = __half22float2(*(__half2*)&c00[jj]);
            float2 f01 = __half22float2(*(__half2*)&c01[jj]);
            float2 f10 = __half22float2(*(__half2*)&c10[jj]);
            float2 f11 = __half22float2(*(__half2*)&c11[jj]);
            float vx = mw.x * f00.x;
            vx = fmaf(mw.y, f01.x, vx);
            vx = fmaf(mw.z, f10.x, vx);
            vx = fmaf(mw.w, f11.x, vx);
            float vy = mw.x * f00.y;
            vy = fmaf(mw.y, f01.y, vy);
            vy = fmaf(mw.z, f10.y, vy);
            vy = fmaf(mw.w, f11.y, vy);
            ov[jj] = h2u(__floats2half2_rn(vx, vy));
        }
    } else {  // rare: a sampled row falls outside the staged window
        int mi = sMI[u];
        int cy0 = mi & 63, cy1 = (mi >> 6) & 63;
        int cx0 = (mi >> 12) & 63, cx1 = (mi >> 18) & 63;
        #pragma unroll
        for (int jj = 0; jj < 4; jj++) {
            float vv[2];
            #pragma unroll
            for (int h = 0; h < 2; h++) {
                int ch = 2 * jj + h;
                const float* xp = xcb + ch * 4096;
                float v = mw.x * xp[cy0 * 64 + cx0];
                v = fmaf(mw.y, xp[cy0 * 64 + cx1], v);
                v = fmaf(mw.z, xp[cy1 * 64 + cx0], v);
                vv[h] = fmaf(mw.w, xp[cy1 * 64 + cx1], v);
            }
            ov[jj] = h2u(__floats2half2_rn(vv[0], vv[1]));
        }
    }
    *(uint4*)(bD + px * BSTR + tap * 4) = make_uint4(ov[0], ov[1], ov[2], ov[3]);
}

__global__ __launch_bounds__(THREADS, 2)
void deform_conv_pa(const float* __restrict__ x,
                    const float* __restrict__ offs,
                    float* __restrict__ out) {
    extern __shared__ char smem[];
    int*      sMI = (int*)(smem + OFF_MI);
    float4*   sMW = (float4*)(smem + OFF_MW);
    uint2*    sAD = (uint2*)(smem + OFF_AD);
    uint4*    sX4 = (uint4*)(smem + OFF_X);
    uint32_t* sBu = (uint32_t*)(smem + OFF_B);

    const int t = threadIdx.x, lane = t & 31, warp = t >> 5;
    const int b = blockIdx.x >> 5, ho2 = blockIdx.x & 31;
    const int lo = min(max(2 * ho2 - 5, 0), 64 - XROWS);
    const float* xg = x + b * 524288;

    // ---- tap metadata + precomputed window addresses ----
    const float* ob = offs + b * 18 * 4096;
    for (int i = t; i < 1152; i += THREADS) {
        int k = i >> 7, rp = i & 127, r = rp >> 6, p = rp & 63;
        int ho = 2 * ho2 + r;
        float dy = ob[(2 * k) * 4096 + ho * 64 + p];
        float dx = ob[(2 * k + 1) * 4096 + ho * 64 + p];
        float py = (float)(ho - 1 + k / 3) + dy;
        float px = (float)(p  - 1 + k % 3) + dx;
        float fy = floorf(py), fx = floorf(px);
        int y0 = (int)fy, x0 = (int)fx;
        float wy = py - fy, wx = px - fx;
        float wy1 = 1.f - wy, wx1 = 1.f - wx;
        float w00 = wy1 * wx1, w01 = wy1 * wx, w10 = wy * wx1, w11 = wy * wx;
        bool vy0 = (unsigned)y0       < 64u, vy1 = (unsigned)(y0 + 1) < 64u;
        bool vx0 = (unsigned)x0       < 64u, vx1 = (unsigned)(x0 + 1) < 64u;
        if (!(vy0 && vx0)) w00 = 0.f;
        if (!(vy0 && vx1)) w01 = 0.f;
        if (!(vy1 && vx0)) w10 = 0.f;
        if (!(vy1 && vx1)) w11 = 0.f;
        int cy0 = min(max(y0, 0), 63), cy1 = min(max(y0 + 1, 0), 63);
        int cx0 = min(max(x0, 0), 63), cx1 = min(max(x0 + 1, 0), 63);
        sMI[i] = cy0 | (cy1 << 6) | (cx0 << 12) | (cx1 << 18);
        sMW[i] = make_float4(w00, w01, w10, w11);
        int wr0 = cy0 - lo, wr1 = cy1 - lo;
        bool in = ((unsigned)wr0 < (unsigned)XROWS) &&
                  ((unsigned)wr1 < (unsigned)XROWS);
        uint2 ad;
        if (in) {
            uint32_t a00 = (uint32_t)((wr0 * 64 + SWZ(cx0)) * 16);
            uint32_t a01 = (uint32_t)((wr0 * 64 + SWZ(cx1)) * 16);
            uint32_t a10 = (uint32_t)((wr1 * 64 + SWZ(cx0)) * 16);
            uint32_t a11 = (uint32_t)((wr1 * 64 + SWZ(cx1)) * 16);
            ad = make_uint2(a00 | (a01 << 16), a10 | (a11 << 16));
        } else {
            ad = make_uint2(0xFFFFFFFFu, 0u);
        }
        sAD[i] = ad;
    }

    // ---- prologue: stage windows 0 and 1 (416 units) ----
    #pragma unroll
    for (int j = 0; j < 2; j++) {
        int idx = j * THREADS + t;
        if (idx < 416) {
            int w = idx >= 208;
            stage_unit(sX4 + w * XWIN4, xg + w * 8 * 4096, idx - w * 208, lo);
        }
    }
    __syncthreads();

    const int g = lane >> 2, tq = lane & 3;
    const int warpM = warp >> 1, warpN = warp & 1;
    float acc[2][8][4];
    #pragma unroll
    for (int m = 0; m < 2; m++)
        #pragma unroll
        for (int n = 0; n < 8; n++)
            #pragma unroll
            for (int c = 0; c < 4; c++) acc[m][n][c] = 0.f;

    // ldmatrix per-thread address offsets (bytes within a B buffer)
    const uint32_t sBuAddr = (uint32_t)__cvta_generic_to_shared(sBu);
    const int rr = lane & 7;
    const uint32_t bOffJ = (uint32_t)((warpN * 64 + ((lane >> 4) & 1) * 8 + rr) * 144
                                      + ((lane >> 3) & 1) * 16);
    const uint32_t bOffT = (uint32_t)((warpN * 64 + ((lane >> 3) & 3) * 8 + rr) * 144 + 128);

    // gather step 0
    #pragma unroll
    for (int u = 0; u < 5; u++) {
        int idx = u * THREADS + t;
        if (idx < 1152)
            gather_unit((const char*)sX4, xg, sBu, sAD, sMI, sMW, idx);
    }

    // ---- main pipeline: 16 steps, one cg8 each ----
    for (int s = 0; s < NSTEP; s++) {
        __syncthreads();   // B(s) + X window s+1 ready

        // ---- MMA step s ----
        {
            const uint32_t bBase = sBuAddr + (s & 1) * BBUFB;
            const int aRow = warpM * 32 + g;
            #pragma unroll
            for (int half = 0; half < 2; half++) {
                uint4 Ar[4];
                #pragma unroll
                for (int r4 = 0; r4 < 4; r4++)
                    Ar[r4] = __ldg(&g_wtA[((s * 2 + half) * 128 + aRow + r4 * 8) * 4 + tq]);
                const uint32_t* Au = (const uint32_t*)Ar;
                #pragma unroll
                for (int jj = 0; jj < 2; jj++) {
                    const int j = 2 * half + jj;
                    uint32_t bb[16];
                    #pragma unroll
                    for (int i = 0; i < 4; i++)
                        ldsm4(bb + 4 * i, bBase + bOffJ + j * 32 + i * 2304);
                    uint32_t a00 = Au[0 * 4 + 2 * jj], a02 = Au[0 * 4 + 2 * jj + 1];
                    uint32_t a01 = Au[1 * 4 + 2 * jj], a03 = Au[1 * 4 + 2 * jj + 1];
                    uint32_t a10 = Au[2 * 4 + 2 * jj], a12 = Au[2 * 4 + 2 * jj + 1];
                    uint32_t a11 = Au[3 * 4 + 2 * jj], a13 = Au[3 * 4 + 2 * jj + 1];
                    #pragma unroll
                    for (int nt = 0; nt < 8; nt++) {
                        uint32_t b0 = bb[4 * (nt >> 1) + (nt & 1) * 2];
                        uint32_t b1 = bb[4 * (nt >> 1) + (nt & 1) * 2 + 1];
                        mma_k16(acc[0][nt], a00, a01, a02, a03, b0, b1);
                        mma_k16(acc[1][nt], a10, a11, a12, a13, b0, b1);
                    }
                }
            }
            {   // tap-8 tail (k8)
                uint32_t A8[4];
                #pragma unroll
                for (int r4 = 0; r4 < 4; r4++)
                    A8[r4] = __ldg(&g_wtA8[(s * 128 + aRow + r4 * 8) * 4 + tq]);
                uint32_t bb[8];
                #pragma unroll
                for (int i2 = 0; i2 < 2; i2++)
                    ldsm4(bb + 4 * i2, bBase + bOffT + i2 * 4608);
                #pragma unroll
                for (int nt = 0; nt < 8; nt++) {
                    mma_k8(acc[0][nt], A8[0], A8[1], bb[nt]);
                    mma_k8(acc[1][nt], A8[2], A8[3], bb[nt]);
                }
            }
        }

        if (s == NSTEP - 1) break;

        // ---- all warps: gather step s+1 from window s+1 ----
        {
            const char* xwb = (const char*)sX4 + ((s + 1) & 1) * XWINB;
            const float* xcb = xg + (s + 1) * 8 * 4096;
            uint32_t* bD = sBu + ((s + 1) & 1) * BBUF;
            #pragma unroll
            for (int u = 0; u < 5; u++) {
                int idx = u * THREADS + t;
                if (idx < 1152)
                    gather_unit(xwb, xcb, bD, sAD, sMI, sMW, idx);
            }
        }
        // ---- all warps: stage window s+2 into buffer s&1 (window s dead) ----
        if (s + 2 < NSTEP && t < 208)
            stage_unit(sX4 + (s & 1) * XWIN4, xg + (s + 2) * 8 * 4096, t, lo);
    }

    // ---- epilogue: D[m=cout][n] -> out row 2*ho2+warpN ----
    float* o = out + b * 524288 + (2 * ho2 + warpN) * 64;
    #pragma unroll
    for (int mt = 0; mt < 2; mt++) {
        int row0 = warpM * 32 + mt * 16 + g;
        #pragma unroll
        for (int nt = 0; nt < 8; nt++) {
            int p = nt * 8 + 2 * tq;
            *(float2*)(o + row0 * 4096 + p) =
                make_float2(acc[mt][nt][0], acc[mt][nt][1]);
            *(float2*)(o + (row0 + 8) * 4096 + p) =
                make_float2(acc[mt][nt][2], acc[mt][nt][3]);
        }
    }
}

extern "C" void kernel_launch(void* const* d_in, const int* in_sizes, int n_in,
                              void* d_out, int out_size) {
    const float* x    = (const float*)d_in[0];
    const float* offs = (const float*)d_in[1];
    const float* wgt  = (const float*)d_in[2];
    wt_permute<<<(NSTEP * 128 * 4 + 255) / 256, 256>>>(wgt);
    cudaFuncSetAttribute(deform_conv_pa,
                         cudaFuncAttributeMaxDynamicSharedMemorySize, SMEM_TOTAL);
    deform_conv_pa<<<256, THREADS, SMEM_TOTAL>>>(x, offs, (float*)d_out);
}

// round 14
// speedup vs baseline: 1.0305x; 1.0305x over previous
#include <cuda_runtime.h>
#include <cuda_fp16.h>
#include <cstdint>

// Deformable conv2d B=8, Cin=Cout=128, H=W=64, 3x3 s1 p1 DG=1.
// f16 HMMA m16n8k16 (fp32 accum). Channel-packed fp16 X window (LDS.128 = 8ch),
// precomputed gather addresses, ldmatrix B feed, lane-contig A LDG.128.
// Phase-staggered warps: w0-3 gather->stage->MMA, w4-7 MMA->gather.
// One CTA per (b, ho-pair): 256 CTAs, 16 steps of K=72.

#define THREADS 256
static constexpr int KTOT = 1152;
static constexpr int NSTEP = 16;            // one cg8 per step, K=72

static constexpr int XROWS = 13;
static constexpr int XWIN4 = XROWS * 64;    // uint4 per window buffer = 832
static constexpr int XWINB = XWIN4 * 16;    // bytes per window buffer = 13312
static constexpr int BSTR  = 36;            // B row stride in u32 (72 half, 144B)
static constexpr int BBUF  = 128 * BSTR;    // 4608 u32 per buffer
static constexpr int BBUFB = BBUF * 4;      // 18432 B

// smem layout (bytes)
static constexpr int OFF_MI = 0;            // int[1152]      4608
static constexpr int OFF_MW = 4608;         // float4[1152]  18432
static constexpr int OFF_AD = 23040;        // uint2[1152]    9216
static constexpr int OFF_X  = 32256;        // 2 x 13312 =   26624
static constexpr int OFF_B  = 58880;        // 2 x 18432 =   36864
static constexpr int SMEM_TOTAL = 95744;

#define SWZ(x) ((x) ^ (((x) >> 3) & 7))

// A weights, lane-contiguous uint4: [step][tapgrp(2)][row(128)][tq(4)]
__device__ uint4    g_wtA[NSTEP * 2 * 128 * 4];
// tap-8 tail: [step][row][tq]
__device__ uint32_t g_wtA8[NSTEP * 128 * 4];

__device__ __forceinline__ void mma_k16(float* d, uint32_t a0, uint32_t a1,
                                        uint32_t a2, uint32_t a3,
                                        uint32_t b0, uint32_t b1) {
    asm volatile(
        "mma.sync.aligned.m16n8k16.row.col.f32.f16.f16.f32 "
        "{%0,%1,%2,%3}, {%4,%5,%6,%7}, {%8,%9}, {%0,%1,%2,%3};"
        : "+f"(d[0]), "+f"(d[1]), "+f"(d[2]), "+f"(d[3])
        : "r"(a0), "r"(a1), "r"(a2), "r"(a3), "r"(b0), "r"(b1));
}
__device__ __forceinline__ void mma_k8(float* d, uint32_t a0, uint32_t a1,
                                       uint32_t b0) {
    asm volatile(
        "mma.sync.aligned.m16n8k8.row.col.f32.f16.f16.f32 "
        "{%0,%1,%2,%3}, {%4,%5}, {%6}, {%0,%1,%2,%3};"
        : "+f"(d[0]), "+f"(d[1]), "+f"(d[2]), "+f"(d[3])
        : "r"(a0), "r"(a1), "r"(b0));
}
__device__ __forceinline__ void ldsm4(uint32_t* r, uint32_t addr) {
    asm volatile(
        "ldmatrix.sync.aligned.m8n8.x4.shared.b16 {%0,%1,%2,%3}, [%4];"
        : "=r"(r[0]), "=r"(r[1]), "=r"(r[2]), "=r"(r[3]) : "r"(addr));
}
__device__ __forceinline__ uint32_t h2u(__half2 h) { return *(uint32_t*)&h; }

__global__ void wt_permute(const float* __restrict__ w) {
    int idx = blockIdx.x * 256 + threadIdx.x;
    if (idx >= NSTEP * 128 * 4) return;
    int tq = idx & 3, row = (idx >> 2) & 127, s = idx >> 9;
    int ch0 = s * 8 + 2 * tq;
    const float* w0 = w + row * KTOT + ch0 * 9;
    const float* w1 = w0 + 9;
    #pragma unroll
    for (int tg = 0; tg < 2; tg++) {
        uint4 v;
        v.x = h2u(__floats2half2_rn(w0[4 * tg + 0], w1[4 * tg + 0]));
        v.y = h2u(__floats2half2_rn(w0[4 * tg + 1], w1[4 * tg + 1]));
        v.z = h2u(__floats2half2_rn(w0[4 * tg + 2], w1[4 * tg + 2]));
        v.w = h2u(__floats2half2_rn(w0[4 * tg + 3], w1[4 * tg + 3]));
        g_wtA[((s * 2 + tg) * 128 + row) * 4 + tq] = v;
    }
    g_wtA8[idx] = h2u(__floats2half2_rn(w0[8], w1[8]));
}

// stage one (row, x-quad) of a window: 8 coalesced LDG.128 + 4 swizzled STS.128
__device__ __forceinline__ void stage_unit(uint4* xw4, const float* xcb,
                                           int u, int lo) {
    int r = u >> 4, q = u & 15;
    const float* src = xcb + (lo + r) * 64 + 4 * q;
    uint32_t h[4][4];
    #pragma unroll
    for (int p = 0; p < 4; p++) {
        float4 a = *(const float4*)(src + (2 * p) * 4096);
        float4 b = *(const float4*)(src + (2 * p + 1) * 4096);
        h[0][p] = h2u(__floats2half2_rn(a.x, b.x));
        h[1][p] = h2u(__floats2half2_rn(a.y, b.y));
        h[2][p] = h2u(__floats2half2_rn(a.z, b.z));
        h[3][p] = h2u(__floats2half2_rn(a.w, b.w));
    }
    #pragma unroll
    for (int i = 0; i < 4; i++) {
        int x = 4 * q + i;
        xw4[r * 64 + SWZ(x)] = make_uint4(h[i][0], h[i][1], h[i][2], h[i][3]);
    }
}

// gather one (tap, px): precomputed addresses, 4 LDS.128 corners -> 1 STS.128
__device__ __forceinline__ void gather_unit(const char* xwb, const float* xcb,
                                            uint32_t* bD, const uint2* sAD,
                                            const int* sMI, const float4* sMW,
                                            int idx) {
    const int px = idx & 127, tap = idx >> 7;
    const int u = tap * 128 + px;
    uint2 ad = sAD[u];
    float4 mw = sMW[u];
    uint32_t ov[4];
    if (ad.x != 0xFFFFFFFFu) {
        uint32_t c00[4], c01[4], c10[4], c11[4];
        *(uint4*)c00 = *(const uint4*)(xwb + (ad.x & 0xFFFFu));
        *(uint4*)c01 = *(const uint4*)(xwb + (ad.x >> 16));
        *(uint4*)c10 = *(const uint4*)(xwb + (ad.y & 0xFFFFu));
        *(uint4*)c11 = *(const uint4*)(xwb + (ad.y >> 16));
        #pragma unroll
        for (int jj = 0; jj < 4; jj++) {
            float2 f00 = __half22float2(*(__half2*)&c00[jj]);
            float2 f01 = __half22float2(*(__half2*)&c01[jj]);
            float2 f10 = __half22float2(*(__half2*)&c10[jj]);
            float2 f11 = __half22float2(*(__half2*)&c11[jj]);
            float vx = mw.x * f00.x;
            vx = fmaf(mw.y, f01.x, vx);
            vx = fmaf(mw.z, f10.x, vx);
            vx = fmaf(mw.w, f11.x, vx);
            float vy = mw.x * f00.y;
            vy = fmaf(mw.y, f01.y, vy);
            vy = fmaf(mw.z, f10.y, vy);
            vy = fmaf(mw.w, f11.y, vy);
            ov[jj] = h2u(__floats2half2_rn(vx, vy));
        }
    } else {  // rare: a sampled row falls outside the staged window
        int mi = sMI[u];
        int cy0 = mi & 63, cy1 = (mi >> 6) & 63;
        int cx0 = (mi >> 12) & 63, cx1 = (mi >> 18) & 63;
        #pragma unroll
        for (int jj = 0; jj < 4; jj++) {
            float vv[2];
            #pragma unroll
            for (int h = 0; h < 2; h++) {
                int ch = 2 * jj + h;
                const float* xp = xcb + ch * 4096;
                float v = mw.x * xp[cy0 * 64 + cx0];
                v = fmaf(mw.y, xp[cy0 * 64 + cx1], v);
                v = fmaf(mw.z, xp[cy1 * 64 + cx0], v);
                vv[h] = fmaf(mw.w, xp[cy1 * 64 + cx1], v);
            }
            ov[jj] = h2u(__floats2half2_rn(vv[0], vv[1]));
        }
    }
    *(uint4*)(bD + px * BSTR + tap * 4) = make_uint4(ov[0], ov[1], ov[2], ov[3]);
}

__global__ __launch_bounds__(THREADS, 2)
void deform_conv_st(const float* __restrict__ x,
                    const float* __restrict__ offs,
                    float* __restrict__ out) {
    extern __shared__ char smem[];
    int*      sMI = (int*)(smem + OFF_MI);
    float4*   sMW = (float4*)(smem + OFF_MW);
    uint2*    sAD = (uint2*)(smem + OFF_AD);
    uint4*    sX4 = (uint4*)(smem + OFF_X);
    uint32_t* sBu = (uint32_t*)(smem + OFF_B);

    const int t = threadIdx.x, lane = t & 31, warp = t >> 5;
    const int b = blockIdx.x >> 5, ho2 = blockIdx.x & 31;
    const int lo = min(max(2 * ho2 - 5, 0), 64 - XROWS);
    const float* xg = x + b * 524288;

    // ---- tap metadata + precomputed window addresses ----
    const float* ob = offs + b * 18 * 4096;
    for (int i = t; i < 1152; i += THREADS) {
        int k = i >> 7, rp = i & 127, r = rp >> 6, p = rp & 63;
        int ho = 2 * ho2 + r;
        float dy = ob[(2 * k) * 4096 + ho * 64 + p];
        float dx = ob[(2 * k + 1) * 4096 + ho * 64 + p];
        float py = (float)(ho - 1 + k / 3) + dy;
        float px = (float)(p  - 1 + k % 3) + dx;
        float fy = floorf(py), fx = floorf(px);
        int y0 = (int)fy, x0 = (int)fx;
        float wy = py - fy, wx = px - fx;
        float wy1 = 1.f - wy, wx1 = 1.f - wx;
        float w00 = wy1 * wx1, w01 = wy1 * wx, w10 = wy * wx1, w11 = wy * wx;
        bool vy0 = (unsigned)y0       < 64u, vy1 = (unsigned)(y0 + 1) < 64u;
        bool vx0 = (unsigned)x0       < 64u, vx1 = (unsigned)(x0 + 1) < 64u;
        if (!(vy0 && vx0)) w00 = 0.f;
        if (!(vy0 && vx1)) w01 = 0.f;
        if (!(vy1 && vx0)) w10 = 0.f;
        if (!(vy1 && vx1)) w11 = 0.f;
        int cy0 = min(max(y0, 0), 63), cy1 = min(max(y0 + 1, 0), 63);
        int cx0 = min(max(x0, 0), 63), cx1 = min(max(x0 + 1, 0), 63);
        sMI[i] = cy0 | (cy1 << 6) | (cx0 << 12) | (cx1 << 18);
        sMW[i] = make_float4(w00, w01, w10, w11);
        int wr0 = cy0 - lo, wr1 = cy1 - lo;
        bool in = ((unsigned)wr0 < (unsigned)XROWS) &&
                  ((unsigned)wr1 < (unsigned)XROWS);
        uint2 ad;
        if (in) {
            uint32_t a00 = (uint32_t)((wr0 * 64 + SWZ(cx0)) * 16);
            uint32_t a01 = (uint32_t)((wr0 * 64 + SWZ(cx1)) * 16);
            uint32_t a10 = (uint32_t)((wr1 * 64 + SWZ(cx0)) * 16);
            uint32_t a11 = (uint32_t)((wr1 * 64 + SWZ(cx1)) * 16);
            ad = make_uint2(a00 | (a01 << 16), a10 | (a11 << 16));
        } else {
            ad = make_uint2(0xFFFFFFFFu, 0u);
        }
        sAD[i] = ad;
    }

    // ---- prologue: stage windows 0 and 1 (416 units) ----
    #pragma unroll
    for (int j = 0; j < 2; j++) {
        int idx = j * THREADS + t;
        if (idx < 416) {
            int w = idx >= 208;
            stage_unit(sX4 + w * XWIN4, xg + w * 8 * 4096, idx - w * 208, lo);
        }
    }
    __syncthreads();

    const int g = lane >> 2, tq = lane & 3;
    const int warpM = warp >> 1, warpN = warp & 1;
    float acc[2][8][4];
    #pragma unroll
    for (int m = 0; m < 2; m++)
        #pragma unroll
        for (int n = 0; n < 8; n++)
            #pragma unroll
            for (int c = 0; c < 4; c++) acc[m][n][c] = 0.f;

    // ldmatrix per-thread address offsets (bytes within a B buffer)
    const uint32_t sBuAddr = (uint32_t)__cvta_generic_to_shared(sBu);
    const int rr = lane & 7;
    const uint32_t bOffJ = (uint32_t)((warpN * 64 + ((lane >> 4) & 1) * 8 + rr) * 144
                                      + ((lane >> 3) & 1) * 16);
    const uint32_t bOffT = (uint32_t)((warpN * 64 + ((lane >> 3) & 3) * 8 + rr) * 144 + 128);

    // unit assignment: warps 0-3 -> 4 units (0..511); warps 4-7 -> 5 units (512..1151)
    const bool loHalf = (warp < 4);
    const int tH = t & 127;

    // gather step 0
    if (loHalf) {
        #pragma unroll
        for (int u = 0; u < 4; u++)
            gather_unit((const char*)sX4, xg, sBu, sAD, sMI, sMW, u * 128 + tH);
    } else {
        #pragma unroll
        for (int u = 0; u < 5; u++)
            gather_unit((const char*)sX4, xg, sBu, sAD, sMI, sMW, 512 + u * 128 + tH);
    }

    // ---- main pipeline: 16 steps, one cg8 each ----
    for (int s = 0; s < NSTEP; s++) {
        __syncthreads();   // B(s) + X window s+1 ready; X buffer s&1 dead

        // ---- phase A for warps 0-3: gather(s+1) + stage(s+2) BEFORE MMA ----
        if (loHalf && s < NSTEP - 1) {
            const char* xwb = (const char*)sX4 + ((s + 1) & 1) * XWINB;
            const float* xcb = xg + (s + 1) * 8 * 4096;
            uint32_t* bD = sBu + ((s + 1) & 1) * BBUF;
            #pragma unroll
            for (int u = 0; u < 4; u++)
                gather_unit(xwb, xcb, bD, sAD, sMI, sMW, u * 128 + tH);
            if (s + 2 < NSTEP) {
                uint4* xwn = sX4 + (s & 1) * XWIN4;
                const float* xc2 = xg + (s + 2) * 8 * 4096;
                stage_unit(xwn, xc2, tH, lo);
                if (tH < 80) stage_unit(xwn, xc2, tH + 128, lo);
            }
        }

        // ---- MMA step s (all warps) ----
        {
            const uint32_t bBase = sBuAddr + (s & 1) * BBUFB;
            const int aRow = warpM * 32 + g;
            #pragma unroll
            for (int half = 0; half < 2; half++) {
                uint4 Ar[4];
                #pragma unroll
                for (int r4 = 0; r4 < 4; r4++)
                    Ar[r4] = __ldg(&g_wtA[((s * 2 + half) * 128 + aRow + r4 * 8) * 4 + tq]);
                const uint32_t* Au = (const uint32_t*)Ar;
                #pragma unroll
                for (int jj = 0; jj < 2; jj++) {
                    const int j = 2 * half + jj;
                    uint32_t bb[16];
                    #pragma unroll
                    for (int i = 0; i < 4; i++)
                        ldsm4(bb + 4 * i, bBase + bOffJ + j * 32 + i * 2304);
                    uint32_t a00 = Au[0 * 4 + 2 * jj], a02 = Au[0 * 4 + 2 * jj + 1];
                    uint32_t a01 = Au[1 * 4 + 2 * jj], a03 = Au[1 * 4 + 2 * jj + 1];
                    uint32_t a10 = Au[2 * 4 + 2 * jj], a12 = Au[2 * 4 + 2 * jj + 1];
                    uint32_t a11 = Au[3 * 4 + 2 * jj], a13 = Au[3 * 4 + 2 * jj + 1];
                    #pragma unroll
                    for (int nt = 0; nt < 8; nt++) {
                        uint32_t b0 = bb[4 * (nt >> 1) + (nt & 1) * 2];
                        uint32_t b1 = bb[4 * (nt >> 1) + (nt & 1) * 2 + 1];
                        mma_k16(acc[0][nt], a00, a01, a02, a03, b0, b1);
                        mma_k16(acc[1][nt], a10, a11, a12, a13, b0, b1);
                    }
                }
            }
            {   // tap-8 tail (k8)
                uint32_t A8[4];
                #pragma unroll
                for (int r4 = 0; r4 < 4; r4++)
                    A8[r4] = __ldg(&g_wtA8[(s * 128 + aRow + r4 * 8) * 4 + tq]);
                uint32_t bb[8];
                #pragma unroll
                for (int i2 = 0; i2 < 2; i2++)
                    ldsm4(bb + 4 * i2, bBase + bOffT + i2 * 4608);
                #pragma unroll
                for (int nt = 0; nt < 8; nt++) {
                    mma_k8(acc[0][nt], A8[0], A8[1], bb[nt]);
                    mma_k8(acc[1][nt], A8[2], A8[3], bb[nt]);
                }
            }
        }

        // ---- phase B for warps 4-7: gather(s+1) AFTER MMA ----
        if (!loHalf && s < NSTEP - 1) {
            const char* xwb = (const char*)sX4 + ((s + 1) & 1) * XWINB;
            const float* xcb = xg + (s + 1) * 8 * 4096;
            uint32_t* bD = sBu + ((s + 1) & 1) * BBUF;
            #pragma unroll
            for (int u = 0; u < 5; u++)
                gather_unit(xwb, xcb, bD, sAD, sMI, sMW, 512 + u * 128 + tH);
        }
    }

    // ---- epilogue: D[m=cout][n] -> out row 2*ho2+warpN ----
    float* o = out + b * 524288 + (2 * ho2 + warpN) * 64;
    #pragma unroll
    for (int mt = 0; mt < 2; mt++) {
        int row0 = warpM * 32 + mt * 16 + g;
        #pragma unroll
        for (int nt = 0; nt < 8; nt++) {
            int p = nt * 8 + 2 * tq;
            *(float2*)(o + row0 * 4096 + p) =
                make_float2(acc[mt][nt][0], acc[mt][nt][1]);
            *(float2*)(o + (row0 + 8) * 4096 + p) =
                make_float2(acc[mt][nt][2], acc[mt][nt][3]);
        }
    }
}

extern "C" void kernel_launch(void* const* d_in, const int* in_sizes, int n_in,
                              void* d_out, int out_size) {
    const float* x    = (const float*)d_in[0];
    const float* offs = (const float*)d_in[1];
    const float* wgt  = (const float*)d_in[2];
    wt_permute<<<(NSTEP * 128 * 4 + 255) / 256, 256>>>(wgt);
    cudaFuncSetAttribute(deform_conv_st,
                         cudaFuncAttributeMaxDynamicSharedMemorySize, SMEM_TOTAL);
    deform_conv_st<<<256, THREADS, SMEM_TOTAL>>>(x, offs, (float*)d_out);
}

// round 15
// speedup vs baseline: 1.0310x; 1.0005x over previous
#include <cuda_runtime.h>
#include <cuda_fp16.h>
#include <cstdint>

// Deformable conv2d B=8, Cin=Cout=128, H=W=64, 3x3 s1 p1 DG=1.
// Pre-kernel packs x as fp16 channel-groups: g_xpk[b][cg8][y*64+x] = 8ch x 16B.
// Main: gather bilinear corners via LDG.128 from the slab (no smem X window),
// f16 HMMA m16n8k16 (fp32 accum), ldmatrix B feed, lane-contig A LDG.128,
// phase-staggered warps. One CTA per (b, ho-pair): 256 CTAs, 16 steps of K=72.

#define THREADS 256
static constexpr int KTOT = 1152;
static constexpr int NSTEP = 16;            // one cg8 per step, K=72

static constexpr int BSTR  = 36;            // B row stride in u32 (72 half, 144B)
static constexpr int BBUF  = 128 * BSTR;    // 4608 u32 per buffer
static constexpr int BBUFB = BBUF * 4;      // 18432 B

// smem layout (bytes)
static constexpr int OFF_META = 0;          // uint4[1152] = 18432
static constexpr int OFF_B    = 18432;      // 2 x 18432   = 36864
static constexpr int SMEM_TOTAL = 55296;

// channel-packed fp16 x: [b][cg8][y*64+x] -> uint4 = channels {0,1|2,3|4,5|6,7}
__device__ uint4 g_xpk[8 * 16 * 4096];
// A weights, lane-contiguous uint4: [step][tapgrp(2)][row(128)][tq(4)]
__device__ uint4    g_wtA[NSTEP * 2 * 128 * 4];
// tap-8 tail: [step][row][tq]
__device__ uint32_t g_wtA8[NSTEP * 128 * 4];

__device__ __forceinline__ void mma_k16(float* d, uint32_t a0, uint32_t a1,
                                        uint32_t a2, uint32_t a3,
                                        uint32_t b0, uint32_t b1) {
    asm volatile(
        "mma.sync.aligned.m16n8k16.row.col.f32.f16.f16.f32 "
        "{%0,%1,%2,%3}, {%4,%5,%6,%7}, {%8,%9}, {%0,%1,%2,%3};"
        : "+f"(d[0]), "+f"(d[1]), "+f"(d[2]), "+f"(d[3])
        : "r"(a0), "r"(a1), "r"(a2), "r"(a3), "r"(b0), "r"(b1));
}
__device__ __forceinline__ void mma_k8(float* d, uint32_t a0, uint32_t a1,
                                       uint32_t b0) {
    asm volatile(
        "mma.sync.aligned.m16n8k8.row.col.f32.f16.f16.f32 "
        "{%0,%1,%2,%3}, {%4,%5}, {%6}, {%0,%1,%2,%3};"
        : "+f"(d[0]), "+f"(d[1]), "+f"(d[2]), "+f"(d[3])
        : "r"(a0), "r"(a1), "r"(b0));
}
__device__ __forceinline__ void ldsm4(uint32_t* r, uint32_t addr) {
    asm volatile(
        "ldmatrix.sync.aligned.m8n8.x4.shared.b16 {%0,%1,%2,%3}, [%4];"
        : "=r"(r[0]), "=r"(r[1]), "=r"(r[2]), "=r"(r[3]) : "r"(addr));
}
__device__ __forceinline__ uint32_t h2u(__half2 h) { return *(uint32_t*)&h; }
__device__ __forceinline__ __half2 u2h(uint32_t u) { return *(__half2*)&u; }

// ---- pre-kernel 1: weight permute (frag-ordered fp16) ----
__global__ void wt_permute(const float* __restrict__ w) {
    int idx = blockIdx.x * 256 + threadIdx.x;
    if (idx >= NSTEP * 128 * 4) return;
    int tq = idx & 3, row = (idx >> 2) & 127, s = idx >> 9;
    int ch0 = s * 8 + 2 * tq;
    const float* w0 = w + row * KTOT + ch0 * 9;
    const float* w1 = w0 + 9;
    #pragma unroll
    for (int tg = 0; tg < 2; tg++) {
        uint4 v;
        v.x = h2u(__floats2half2_rn(w0[4 * tg + 0], w1[4 * tg + 0]));
        v.y = h2u(__floats2half2_rn(w0[4 * tg + 1], w1[4 * tg + 1]));
        v.z = h2u(__floats2half2_rn(w0[4 * tg + 2], w1[4 * tg + 2]));
        v.w = h2u(__floats2half2_rn(w0[4 * tg + 3], w1[4 * tg + 3]));
        g_wtA[((s * 2 + tg) * 128 + row) * 4 + tq] = v;
    }
    g_wtA8[idx] = h2u(__floats2half2_rn(w0[8], w1[8]));
}

// ---- pre-kernel 2: x channel-pack to fp16 slabs ----
// grid 512 = (b, cg8, yq): 16 rows per CTA. Coalesced in, coalesced out.
__global__ void x_pack(const float* __restrict__ x) {
    __shared__ float sT[8][1024];
    const int t = threadIdx.x;
    const int yq = blockIdx.x & 3, cg = (blockIdx.x >> 2) & 15, b = blockIdx.x >> 6;
    const float* src = x + (b * 128 + cg * 8) * 4096 + yq * 1024;
    #pragma unroll
    for (int i = 0; i < 8; i++) {
        int idx = i * 256 + t;                      // 2048 float4
        int ch = idx >> 8, q = idx & 255;
        *(float4*)&sT[ch][q * 4] = *(const float4*)(src + ch * 4096 + q * 4);
    }
    __syncthreads();
    uint4* dst = g_xpk + (b * 16 + cg) * 4096 + yq * 1024;
    #pragma unroll
    for (int j = 0; j < 4; j++) {
        int pos = j * 256 + t;
        uint4 v;
        v.x = h2u(__floats2half2_rn(sT[0][pos], sT[1][pos]));
        v.y = h2u(__floats2half2_rn(sT[2][pos], sT[3][pos]));
        v.z = h2u(__floats2half2_rn(sT[4][pos], sT[5][pos]));
        v.w = h2u(__floats2half2_rn(sT[6][pos], sT[7][pos]));
        dst[pos] = v;
    }
}

// gather one (tap, px): 1 LDS.128 meta + 4 LDG.128 corners -> 1 STS.128
__device__ __forceinline__ void gather_unit(const uint4* __restrict__ xs,
                                            uint32_t* bD, const uint4* sMETA,
                                            int idx) {
    const int px = idx & 127, tap = idx >> 7;
    uint4 mt = sMETA[tap * 128 + px];
    uint4 q00 = __ldg(xs + (mt.x & 0xFFFFu));
    uint4 q01 = __ldg(xs + (mt.x >> 16));
    uint4 q10 = __ldg(xs + (mt.y & 0xFFFFu));
    uint4 q11 = __ldg(xs + (mt.y >> 16));
    float2 wA = __half22float2(u2h(mt.z));   // (w00, w01)
    float2 wB = __half22float2(u2h(mt.w));   // (w10, w11)
    const uint32_t* c00 = (const uint32_t*)&q00;
    const uint32_t* c01 = (const uint32_t*)&q01;
    const uint32_t* c10 = (const uint32_t*)&q10;
    const uint32_t* c11 = (const uint32_t*)&q11;
    uint32_t ov[4];
    #pragma unroll
    for (int jj = 0; jj < 4; jj++) {
        float2 f00 = __half22float2(u2h(c00[jj]));
        float2 f01 = __half22float2(u2h(c01[jj]));
        float2 f10 = __half22float2(u2h(c10[jj]));
        float2 f11 = __half22float2(u2h(c11[jj]));
        float vx = wA.x * f00.x;
        vx = fmaf(wA.y, f01.x, vx);
        vx = fmaf(wB.x, f10.x, vx);
        vx = fmaf(wB.y, f11.x, vx);
        float vy = wA.x * f00.y;
        vy = fmaf(wA.y, f01.y, vy);
        vy = fmaf(wB.x, f10.y, vy);
        vy = fmaf(wB.y, f11.y, vy);
        ov[jj] = h2u(__floats2half2_rn(vx, vy));
    }
    *(uint4*)(bD + px * BSTR + tap * 4) = make_uint4(ov[0], ov[1], ov[2], ov[3]);
}

__global__ __launch_bounds__(THREADS, 2)
void deform_conv_gp(const float* __restrict__ offs,
                    float* __restrict__ out) {
    extern __shared__ char smem[];
    uint4*    sMETA = (uint4*)(smem + OFF_META);
    uint32_t* sBu   = (uint32_t*)(smem + OFF_B);

    const int t = threadIdx.x, lane = t & 31, warp = t >> 5;
    const int b = blockIdx.x >> 5, ho2 = blockIdx.x & 31;

    // ---- tap metadata: clamped offsets (u16 x4) + fp16 bilinear weights ----
    const float* ob = offs + b * 18 * 4096;
    for (int i = t; i < 1152; i += THREADS) {
        int k = i >> 7, rp = i & 127, r = rp >> 6, p = rp & 63;
        int ho = 2 * ho2 + r;
        float dy = ob[(2 * k) * 4096 + ho * 64 + p];
        float dx = ob[(2 * k + 1) * 4096 + ho * 64 + p];
        float py = (float)(ho - 1 + k / 3) + dy;
        float px = (float)(p  - 1 + k % 3) + dx;
        float fy = floorf(py), fx = floorf(px);
        int y0 = (int)fy, x0 = (int)fx;
        float wy = py - fy, wx = px - fx;
        float wy1 = 1.f - wy, wx1 = 1.f - wx;
        float w00 = wy1 * wx1, w01 = wy1 * wx, w10 = wy * wx1, w11 = wy * wx;
        bool vy0 = (unsigned)y0       < 64u, vy1 = (unsigned)(y0 + 1) < 64u;
        bool vx0 = (unsigned)x0       < 64u, vx1 = (unsigned)(x0 + 1) < 64u;
        if (!(vy0 && vx0)) w00 = 0.f;
        if (!(vy0 && vx1)) w01 = 0.f;
        if (!(vy1 && vx0)) w10 = 0.f;
        if (!(vy1 && vx1)) w11 = 0.f;
        int cy0 = min(max(y0, 0), 63), cy1 = min(max(y0 + 1, 0), 63);
        int cx0 = min(max(x0, 0), 63), cx1 = min(max(x0 + 1, 0), 63);
        uint32_t o00 = (uint32_t)(cy0 * 64 + cx0);
        uint32_t o01 = (uint32_t)(cy0 * 64 + cx1);
        uint32_t o10 = (uint32_t)(cy1 * 64 + cx0);
        uint32_t o11 = (uint32_t)(cy1 * 64 + cx1);
        uint4 mt;
        mt.x = o00 | (o01 << 16);
        mt.y = o10 | (o11 << 16);
        mt.z = h2u(__floats2half2_rn(w00, w01));
        mt.w = h2u(__floats2half2_rn(w10, w11));
        sMETA[i] = mt;
    }
    __syncthreads();

    const int g = lane >> 2, tq = lane & 3;
    const int warpM = warp >> 1, warpN = warp & 1;
    float acc[2][8][4];
    #pragma unroll
    for (int m = 0; m < 2; m++)
        #pragma unroll
        for (int n = 0; n < 8; n++)
            #pragma unroll
            for (int c = 0; c < 4; c++) acc[m][n][c] = 0.f;

    // ldmatrix per-thread address offsets (bytes within a B buffer)
    const uint32_t sBuAddr = (uint32_t)__cvta_generic_to_shared(sBu);
    const int rr = lane & 7;
    const uint32_t bOffJ = (uint32_t)((warpN * 64 + ((lane >> 4) & 1) * 8 + rr) * 144
                                      + ((lane >> 3) & 1) * 16);
    const uint32_t bOffT = (uint32_t)((warpN * 64 + ((lane >> 3) & 3) * 8 + rr) * 144 + 128);

    // unit split: warps 0-3 -> 5 units (0..639); warps 4-7 -> 4 units (640..1151)
    const bool loHalf = (warp < 4);
    const int tH = t & 127;
    const uint4* xsBase = g_xpk + b * 16 * 4096;

    // gather step 0
    if (loHalf) {
        #pragma unroll
        for (int u = 0; u < 5; u++)
            gather_unit(xsBase, sBu, sMETA, u * 128 + tH);
    } else {
        #pragma unroll
        for (int u = 0; u < 4; u++)
            gather_unit(xsBase, sBu, sMETA, 640 + u * 128 + tH);
    }

    // ---- main pipeline: 16 steps, one cg8 each ----
    for (int s = 0; s < NSTEP; s++) {
        __syncthreads();   // B(s) ready; MMA(s-1) done (B buffer s+1 reusable)

        // ---- phase A for warps 0-3: gather(s+1) BEFORE MMA ----
        if (loHalf && s < NSTEP - 1) {
            const uint4* xs = xsBase + (s + 1) * 4096;
            uint32_t* bD = sBu + ((s + 1) & 1) * BBUF;
            #pragma unroll
            for (int u = 0; u < 5; u++)
                gather_unit(xs, bD, sMETA, u * 128 + tH);
        }

        // ---- MMA step s (all warps) ----
        {
            const uint32_t bBase = sBuAddr + (s & 1) * BBUFB;
            const int aRow = warpM * 32 + g;
            #pragma unroll
            for (int half = 0; half < 2; half++) {
                uint4 Ar[4];
                #pragma unroll
                for (int r4 = 0; r4 < 4; r4++)
                    Ar[r4] = __ldg(&g_wtA[((s * 2 + half) * 128 + aRow + r4 * 8) * 4 + tq]);
                const uint32_t* Au = (const uint32_t*)Ar;
                #pragma unroll
                for (int jj = 0; jj < 2; jj++) {
                    const int j = 2 * half + jj;
                    uint32_t bb[16];
                    #pragma unroll
                    for (int i = 0; i < 4; i++)
                        ldsm4(bb + 4 * i, bBase + bOffJ + j * 32 + i * 2304);
                    uint32_t a00 = Au[0 * 4 + 2 * jj], a02 = Au[0 * 4 + 2 * jj + 1];
                    uint32_t a01 = Au[1 * 4 + 2 * jj], a03 = Au[1 * 4 + 2 * jj + 1];
                    uint32_t a10 = Au[2 * 4 + 2 * jj], a12 = Au[2 * 4 + 2 * jj + 1];
                    uint32_t a11 = Au[3 * 4 + 2 * jj], a13 = Au[3 * 4 + 2 * jj + 1];
                    #pragma unroll
                    for (int nt = 0; nt < 8; nt++) {
                        uint32_t b0 = bb[4 * (nt >> 1) + (nt & 1) * 2];
                        uint32_t b1 = bb[4 * (nt >> 1) + (nt & 1) * 2 + 1];
                        mma_k16(acc[0][nt], a00, a01, a02, a03, b0, b1);
                        mma_k16(acc[1][nt], a10, a11, a12, a13, b0, b1);
                    }
                }
            }
            {   // tap-8 tail (k8)
                uint32_t A8[4];
                #pragma unroll
                for (int r4 = 0; r4 < 4; r4++)
                    A8[r4] = __ldg(&g_wtA8[(s * 128 + aRow + r4 * 8) * 4 + tq]);
                uint32_t bb[8];
                #pragma unroll
                for (int i2 = 0; i2 < 2; i2++)
                    ldsm4(bb + 4 * i2, bBase + bOffT + i2 * 4608);
                #pragma unroll
                for (int nt = 0; nt < 8; nt++) {
                    mma_k8(acc[0][nt], A8[0], A8[1], bb[nt]);
                    mma_k8(acc[1][nt], A8[2], A8[3], bb[nt]);
                }
            }
        }

        // ---- phase B for warps 4-7: gather(s+1) AFTER MMA ----
        if (!loHalf && s < NSTEP - 1) {
            const uint4* xs = xsBase + (s + 1) * 4096;
            uint32_t* bD = sBu + ((s + 1) & 1) * BBUF;
            #pragma unroll
            for (int u = 0; u < 4; u++)
                gather_unit(xs, bD, sMETA, 640 + u * 128 + tH);
        }
    }

    // ---- epilogue: D[m=cout][n] -> out row 2*ho2+warpN ----
    float* o = out + b * 524288 + (2 * ho2 + warpN) * 64;
    #pragma unroll
    for (int mt = 0; mt < 2; mt++) {
        int row0 = warpM * 32 + mt * 16 + g;
        #pragma unroll
        for (int nt = 0; nt < 8; nt++) {
            int p = nt * 8 + 2 * tq;
            *(float2*)(o + row0 * 4096 + p) =
                make_float2(acc[mt][nt][0], acc[mt][nt][1]);
            *(float2*)(o + (row0 + 8) * 4096 + p) =
                make_float2(acc[mt][nt][2], acc[mt][nt][3]);
        }
    }
}

extern "C" void kernel_launch(void* const* d_in, const int* in_sizes, int n_in,
                              void* d_out, int out_size) {
    const float* x    = (const float*)d_in[0];
    const float* offs = (const float*)d_in[1];
    const float* wgt  = (const float*)d_in[2];
    wt_permute<<<(NSTEP * 128 * 4 + 255) / 256, 256>>>(wgt);
    x_pack<<<512, 256>>>(x);
    cudaFuncSetAttribute(deform_conv_gp,
                         cudaFuncAttributeMaxDynamicSharedMemorySize, SMEM_TOTAL);
    deform_conv_gp<<<256, THREADS, SMEM_TOTAL>>>(offs, (float*)d_out);
}

// round 16
// speedup vs baseline: 1.0640x; 1.0320x over previous
#include <cuda_runtime.h>
#include <cuda_fp16.h>
#include <cstdint>

// Deformable conv2d B=8, Cin=Cout=128, H=W=64, 3x3 s1 p1 DG=1.
// Fused pre-kernel: packs x as fp16 channel-group slabs + permutes weights.
// Main: gather bilinear corners via LDG.128 from the slab (no smem X window),
// f16 HMMA m16n8k16 (fp32 accum), ldmatrix B feed, lane-contig A LDG.128,
// phase-staggered warps. One CTA per (b, ho-pair): 256 CTAs, 16 steps of K=72.

#define THREADS 256
static constexpr int KTOT = 1152;
static constexpr int NSTEP = 16;            // one cg8 per step, K=72

static constexpr int BSTR  = 36;            // B row stride in u32 (72 half, 144B)
static constexpr int BBUF  = 128 * BSTR;    // 4608 u32 per buffer
static constexpr int BBUFB = BBUF * 4;      // 18432 B

// smem layout (bytes) - main kernel
static constexpr int OFF_META = 0;          // uint4[1152] = 18432
static constexpr int OFF_B    = 18432;      // 2 x 18432   = 36864
static constexpr int SMEM_TOTAL = 55296;

// channel-packed fp16 x: [b][cg8][y*64+x] -> uint4 = channels {0,1|2,3|4,5|6,7}
__device__ uint4 g_xpk[8 * 16 * 4096];
// A weights, lane-contiguous uint4: [step][tapgrp(2)][row(128)][tq(4)]
__device__ uint4    g_wtA[NSTEP * 2 * 128 * 4];
// tap-8 tail: [step][row][tq]
__device__ uint32_t g_wtA8[NSTEP * 128 * 4];

__device__ __forceinline__ void mma_k16(float* d, uint32_t a0, uint32_t a1,
                                        uint32_t a2, uint32_t a3,
                                        uint32_t b0, uint32_t b1) {
    asm volatile(
        "mma.sync.aligned.m16n8k16.row.col.f32.f16.f16.f32 "
        "{%0,%1,%2,%3}, {%4,%5,%6,%7}, {%8,%9}, {%0,%1,%2,%3};"
        : "+f"(d[0]), "+f"(d[1]), "+f"(d[2]), "+f"(d[3])
        : "r"(a0), "r"(a1), "r"(a2), "r"(a3), "r"(b0), "r"(b1));
}
__device__ __forceinline__ void mma_k8(float* d, uint32_t a0, uint32_t a1,
                                       uint32_t b0) {
    asm volatile(
        "mma.sync.aligned.m16n8k8.row.col.f32.f16.f16.f32 "
        "{%0,%1,%2,%3}, {%4,%5}, {%6}, {%0,%1,%2,%3};"
        : "+f"(d[0]), "+f"(d[1]), "+f"(d[2]), "+f"(d[3])
        : "r"(a0), "r"(a1), "r"(b0));
}
__device__ __forceinline__ void ldsm4(uint32_t* r, uint32_t addr) {
    asm volatile(
        "ldmatrix.sync.aligned.m8n8.x4.shared.b16 {%0,%1,%2,%3}, [%4];"
        : "=r"(r[0]), "=r"(r[1]), "=r"(r[2]), "=r"(r[3]) : "r"(addr));
}
__device__ __forceinline__ uint32_t h2u(__half2 h) { return *(uint32_t*)&h; }
__device__ __forceinline__ __half2 u2h(uint32_t u) { return *(__half2*)&u; }

// ---- fused pre-kernel: blocks 0-511 pack x; blocks 512-639 permute weights ----
__global__ void prep(const float* __restrict__ x, const float* __restrict__ w) {
    __shared__ float sbuf[8 * 1024];        // 32 KB, shared by both roles
    const int t = threadIdx.x;
    if (blockIdx.x < 512) {
        // ---- x channel-pack: (b, cg8, yq), 16 rows per CTA ----
        const int yq = blockIdx.x & 3, cg = (blockIdx.x >> 2) & 15,
                  b = blockIdx.x >> 6;
        const float* src = x + (b * 128 + cg * 8) * 4096 + yq * 1024;
        #pragma unroll
        for (int i = 0; i < 8; i++) {
            int idx = i * 256 + t;                  // 2048 float4
            int ch = idx >> 8, q = idx & 255;
            *(float4*)&sbuf[ch * 1024 + q * 4] =
                *(const float4*)(src + ch * 4096 + q * 4);
        }
        __syncthreads();
        uint4* dst = g_xpk + (b * 16 + cg) * 4096 + yq * 1024;
        #pragma unroll
        for (int j = 0; j < 4; j++) {
            int pos = j * 256 + t;
            uint4 v;
            v.x = h2u(__floats2half2_rn(sbuf[0 * 1024 + pos], sbuf[1 * 1024 + pos]));
            v.y = h2u(__floats2half2_rn(sbuf[2 * 1024 + pos], sbuf[3 * 1024 + pos]));
            v.z = h2u(__floats2half2_rn(sbuf[4 * 1024 + pos], sbuf[5 * 1024 + pos]));
            v.w = h2u(__floats2half2_rn(sbuf[6 * 1024 + pos], sbuf[7 * 1024 + pos]));
            dst[pos] = v;
        }
    } else {
        // ---- weight permute: one CTA per cout row ----
        const int co = blockIdx.x - 512;            // 0..127
        // coalesced load of the contiguous 1152-float row
        for (int i = t; i < 288; i += 256)
            *(float4*)&sbuf[i * 4] = *(const float4*)(w + co * KTOT + i * 4);
        __syncthreads();
        if (t < 128) {
            // g_wtA: j = (s, tg, tq)
            int s = t >> 3, tg = (t >> 2) & 1, tq = t & 3;
            int ch0 = s * 8 + 2 * tq;
            const float* w0 = sbuf + ch0 * 9;
            const float* w1 = w0 + 9;
            uint4 v;
            v.x = h2u(__floats2half2_rn(w0[4 * tg + 0], w1[4 * tg + 0]));
            v.y = h2u(__floats2half2_rn(w0[4 * tg + 1], w1[4 * tg + 1]));
            v.z = h2u(__floats2half2_rn(w0[4 * tg + 2], w1[4 * tg + 2]));
            v.w = h2u(__floats2half2_rn(w0[4 * tg + 3], w1[4 * tg + 3]));
            g_wtA[((s * 2 + tg) * 128 + co) * 4 + tq] = v;
        } else if (t < 192) {
            // g_wtA8: j = (s, tq)
            int j = t - 128;
            int s = j >> 2, tq = j & 3;
            int ch0 = s * 8 + 2 * tq;
            g_wtA8[(s * 128 + co) * 4 + tq] =
                h2u(__floats2half2_rn(sbuf[ch0 * 9 + 8], sbuf[(ch0 + 1) * 9 + 8]));
        }
    }
}

// gather one (tap, px): 1 LDS.128 meta + 4 LDG.128 corners -> 1 STS.128
__device__ __forceinline__ void gather_unit(const uint4* __restrict__ xs,
                                            uint32_t* bD, const uint4* sMETA,
                                            int idx) {
    const int px = idx & 127, tap = idx >> 7;
    uint4 mt = sMETA[tap * 128 + px];
    uint4 q00 = __ldg(xs + (mt.x & 0xFFFFu));
    uint4 q01 = __ldg(xs + (mt.x >> 16));
    uint4 q10 = __ldg(xs + (mt.y & 0xFFFFu));
    uint4 q11 = __ldg(xs + (mt.y >> 16));
    float2 wA = __half22float2(u2h(mt.z));   // (w00, w01)
    float2 wB = __half22float2(u2h(mt.w));   // (w10, w11)
    const uint32_t* c00 = (const uint32_t*)&q00;
    const uint32_t* c01 = (const uint32_t*)&q01;
    const uint32_t* c10 = (const uint32_t*)&q10;
    const uint32_t* c11 = (const uint32_t*)&q11;
    uint32_t ov[4];
    #pragma unroll
    for (int jj = 0; jj < 4; jj++) {
        float2 f00 = __half22float2(u2h(c00[jj]));
        float2 f01 = __half22float2(u2h(c01[jj]));
        float2 f10 = __half22float2(u2h(c10[jj]));
        float2 f11 = __half22float2(u2h(c11[jj]));
        float vx = wA.x * f00.x;
        vx = fmaf(wA.y, f01.x, vx);
        vx = fmaf(wB.x, f10.x, vx);
        vx = fmaf(wB.y, f11.x, vx);
        float vy = wA.x * f00.y;
        vy = fmaf(wA.y, f01.y, vy);
        vy = fmaf(wB.x, f10.y, vy);
        vy = fmaf(wB.y, f11.y, vy);
        ov[jj] = h2u(__floats2half2_rn(vx, vy));
    }
    *(uint4*)(bD + px * BSTR + tap * 4) = make_uint4(ov[0], ov[1], ov[2], ov[3]);
}

__global__ __launch_bounds__(THREADS, 2)
void deform_conv_gp(const float* __restrict__ offs,
                    float* __restrict__ out) {
    extern __shared__ char smem[];
    uint4*    sMETA = (uint4*)(smem + OFF_META);
    uint32_t* sBu   = (uint32_t*)(smem + OFF_B);

    const int t = threadIdx.x, lane = t & 31, warp = t >> 5;
    const int b = blockIdx.x >> 5, ho2 = blockIdx.x & 31;

    // ---- tap metadata: clamped offsets (u16 x4) + fp16 bilinear weights ----
    const float* ob = offs + b * 18 * 4096;
    for (int i = t; i < 1152; i += THREADS) {
        int k = i >> 7, rp = i & 127, r = rp >> 6, p = rp & 63;
        int ho = 2 * ho2 + r;
        float dy = ob[(2 * k) * 4096 + ho * 64 + p];
        float dx = ob[(2 * k + 1) * 4096 + ho * 64 + p];
        float py = (float)(ho - 1 + k / 3) + dy;
        float px = (float)(p  - 1 + k % 3) + dx;
        float fy = floorf(py), fx = floorf(px);
        int y0 = (int)fy, x0 = (int)fx;
        float wy = py - fy, wx = px - fx;
        float wy1 = 1.f - wy, wx1 = 1.f - wx;
        float w00 = wy1 * wx1, w01 = wy1 * wx, w10 = wy * wx1, w11 = wy * wx;
        bool vy0 = (unsigned)y0       < 64u, vy1 = (unsigned)(y0 + 1) < 64u;
        bool vx0 = (unsigned)x0       < 64u, vx1 = (unsigned)(x0 + 1) < 64u;
        if (!(vy0 && vx0)) w00 = 0.f;
        if (!(vy0 && vx1)) w01 = 0.f;
        if (!(vy1 && vx0)) w10 = 0.f;
        if (!(vy1 && vx1)) w11 = 0.f;
        int cy0 = min(max(y0, 0), 63), cy1 = min(max(y0 + 1, 0), 63);
        int cx0 = min(max(x0, 0), 63), cx1 = min(max(x0 + 1, 0), 63);
        uint32_t o00 = (uint32_t)(cy0 * 64 + cx0);
        uint32_t o01 = (uint32_t)(cy0 * 64 + cx1);
        uint32_t o10 = (uint32_t)(cy1 * 64 + cx0);
        uint32_t o11 = (uint32_t)(cy1 * 64 + cx1);
        uint4 mt;
        mt.x = o00 | (o01 << 16);
        mt.y = o10 | (o11 << 16);
        mt.z = h2u(__floats2half2_rn(w00, w01));
        mt.w = h2u(__floats2half2_rn(w10, w11));
        sMETA[i] = mt;
    }
    __syncthreads();

    const int g = lane >> 2, tq = lane & 3;
    const int warpM = warp >> 1, warpN = warp & 1;
    float acc[2][8][4];
    #pragma unroll
    for (int m = 0; m < 2; m++)
        #pragma unroll
        for (int n = 0; n < 8; n++)
            #pragma unroll
            for (int c = 0; c < 4; c++) acc[m][n][c] = 0.f;

    // ldmatrix per-thread address offsets (bytes within a B buffer)
    const uint32_t sBuAddr = (uint32_t)__cvta_generic_to_shared(sBu);
    const int rr = lane & 7;
    const uint32_t bOffJ = (uint32_t)((warpN * 64 + ((lane >> 4) & 1) * 8 + rr) * 144
                                      + ((lane >> 3) & 1) * 16);
    const uint32_t bOffT = (uint32_t)((warpN * 64 + ((lane >> 3) & 3) * 8 + rr) * 144 + 128);

    // unit split: warps 0-3 -> 5 units (0..639); warps 4-7 -> 4 units (640..1151)
    const bool loHalf = (warp < 4);
    const int tH = t & 127;
    const uint4* xsBase = g_xpk + b * 16 * 4096;

    // gather step 0
    if (loHalf) {
        #pragma unroll
        for (int u = 0; u < 5; u++)
            gather_unit(xsBase, sBu, sMETA, u * 128 + tH);
    } else {
        #pragma unroll
        for (int u = 0; u < 4; u++)
            gather_unit(xsBase, sBu, sMETA, 640 + u * 128 + tH);
    }

    // ---- main pipeline: 16 steps, one cg8 each ----
    for (int s = 0; s < NSTEP; s++) {
        __syncthreads();   // B(s) ready; MMA(s-1) done (B buffer s+1 reusable)

        // ---- phase A for warps 0-3: gather(s+1) BEFORE MMA ----
        if (loHalf && s < NSTEP - 1) {
            const uint4* xs = xsBase + (s + 1) * 4096;
            uint32_t* bD = sBu + ((s + 1) & 1) * BBUF;
            #pragma unroll
            for (int u = 0; u < 5; u++)
                gather_unit(xs, bD, sMETA, u * 128 + tH);
        }

        // ---- MMA step s (all warps) ----
        {
            const uint32_t bBase = sBuAddr + (s & 1) * BBUFB;
            const int aRow = warpM * 32 + g;
            #pragma unroll
            for (int half = 0; half < 2; half++) {
                uint4 Ar[4];
                #pragma unroll
                for (int r4 = 0; r4 < 4; r4++)
                    Ar[r4] = __ldg(&g_wtA[((s * 2 + half) * 128 + aRow + r4 * 8) * 4 + tq]);
                const uint32_t* Au = (const uint32_t*)Ar;
                #pragma unroll
                for (int jj = 0; jj < 2; jj++) {
                    const int j = 2 * half + jj;
                    uint32_t bb[16];
                    #pragma unroll
                    for (int i = 0; i < 4; i++)
                        ldsm4(bb + 4 * i, bBase + bOffJ + j * 32 + i * 2304);
                    uint32_t a00 = Au[0 * 4 + 2 * jj], a02 = Au[0 * 4 + 2 * jj + 1];
                    uint32_t a01 = Au[1 * 4 + 2 * jj], a03 = Au[1 * 4 + 2 * jj + 1];
                    uint32_t a10 = Au[2 * 4 + 2 * jj], a12 = Au[2 * 4 + 2 * jj + 1];
                    uint32_t a11 = Au[3 * 4 + 2 * jj], a13 = Au[3 * 4 + 2 * jj + 1];
                    #pragma unroll
                    for (int nt = 0; nt < 8; nt++) {
                        uint32_t b0 = bb[4 * (nt >> 1) + (nt & 1) * 2];
                        uint32_t b1 = bb[4 * (nt >> 1) + (nt & 1) * 2 + 1];
                        mma_k16(acc[0][nt], a00, a01, a02, a03, b0, b1);
                        mma_k16(acc[1][nt], a10, a11, a12, a13, b0, b1);
                    }
                }
            }
            {   // tap-8 tail (k8)
                uint32_t A8[4];
                #pragma unroll
                for (int r4 = 0; r4 < 4; r4++)
                    A8[r4] = __ldg(&g_wtA8[(s * 128 + aRow + r4 * 8) * 4 + tq]);
                uint32_t bb[8];
                #pragma unroll
                for (int i2 = 0; i2 < 2; i2++)
                    ldsm4(bb + 4 * i2, bBase + bOffT + i2 * 4608);
                #pragma unroll
                for (int nt = 0; nt < 8; nt++) {
                    mma_k8(acc[0][nt], A8[0], A8[1], bb[nt]);
                    mma_k8(acc[1][nt], A8[2], A8[3], bb[nt]);
                }
            }
        }

        // ---- phase B for warps 4-7: gather(s+1) AFTER MMA ----
        if (!loHalf && s < NSTEP - 1) {
            const uint4* xs = xsBase + (s + 1) * 4096;
            uint32_t* bD = sBu + ((s + 1) & 1) * BBUF;
            #pragma unroll
            for (int u = 0; u < 4; u++)
                gather_unit(xs, bD, sMETA, 640 + u * 128 + tH);
        }
    }

    // ---- epilogue: D[m=cout][n] -> out row 2*ho2+warpN ----
    float* o = out + b * 524288 + (2 * ho2 + warpN) * 64;
    #pragma unroll
    for (int mt = 0; mt < 2; mt++) {
        int row0 = warpM * 32 + mt * 16 + g;
        #pragma unroll
        for (int nt = 0; nt < 8; nt++) {
            int p = nt * 8 + 2 * tq;
            *(float2*)(o + row0 * 4096 + p) =
                make_float2(acc[mt][nt][0], acc[mt][nt][1]);
            *(float2*)(o + (row0 + 8) * 4096 + p) =
                make_float2(acc[mt][nt][2], acc[mt][nt][3]);
        }
    }
}

extern "C" void kernel_launch(void* const* d_in, const int* in_sizes, int n_in,
                              void* d_out, int out_size) {
    const float* x    = (const float*)d_in[0];
    const float* offs = (const float*)d_in[1];
    const float* wgt  = (const float*)d_in[2];
    prep<<<640, 256>>>(x, wgt);
    cudaFuncSetAttribute(deform_conv_gp,
                         cudaFuncAttributeMaxDynamicSharedMemorySize, SMEM_TOTAL);
    deform_conv_gp<<<256, THREADS, SMEM_TOTAL>>>(offs, (float*)d_out);
}